// round 1
// baseline (speedup 1.0000x reference)
#include <cuda_runtime.h>
#include <math_constants.h>

// Shapes (fixed by problem)
#define B 32
#define T 512
#define D 512
#define H 8
#define S 196
#define LAYER_ID 2
#define K_TOP 51   // int(0.1 * 512)

// Scratch (allocation-free rule: __device__ globals)
__device__ float g_w[B * T];
__device__ int   g_selidx[B * K_TOP];
__device__ float g_selw[B * K_TOP];
__device__ int   g_m[B];

// ---------------------------------------------------------------------------
// Kernel 1: cosine weights per (b, t), masked to -1 where seq_mask is false.
// One warp per t, 8 warps/block, grid (T/8, B). fore_rep row staged in smem.
// ---------------------------------------------------------------------------
__global__ __launch_bounds__(256) void k_weights(
    const float* __restrict__ fore,     // (B, D)
    const float* __restrict__ embed,    // (B, T, D)
    const int*   __restrict__ targets)  // (B, T+1) int32
{
    __shared__ float sy[D];
    const int b    = blockIdx.y;
    const int tid  = threadIdx.x;
    const int lane = tid & 31;
    const int t    = blockIdx.x * 8 + (tid >> 5);

    for (int i = tid; i < D; i += 256) sy[i] = fore[b * D + i];
    __syncthreads();

    // y norm (redundant per warp, cheap smem reads)
    float yn2 = 0.f;
    for (int i = lane; i < D; i += 32) { float v = sy[i]; yn2 += v * v; }

    const float4* xrow = reinterpret_cast<const float4*>(embed + ((size_t)b * T + t) * D);
    const float4* yrow = reinterpret_cast<const float4*>(sy);
    float num = 0.f, xn2 = 0.f;
#pragma unroll
    for (int i = 0; i < 4; i++) {
        float4 xv = xrow[lane + i * 32];
        float4 yv = yrow[lane + i * 32];
        num += xv.x * yv.x + xv.y * yv.y + xv.z * yv.z + xv.w * yv.w;
        xn2 += xv.x * xv.x + xv.y * xv.y + xv.z * xv.z + xv.w * xv.w;
    }
#pragma unroll
    for (int o = 16; o; o >>= 1) {
        num += __shfl_xor_sync(0xffffffffu, num, o);
        xn2 += __shfl_xor_sync(0xffffffffu, xn2, o);
        yn2 += __shfl_xor_sync(0xffffffffu, yn2, o);
    }
    if (lane == 0) {
        float xn = fmaxf(sqrtf(xn2), 1e-8f);
        float yn = fmaxf(sqrtf(yn2), 1e-8f);
        float w  = num / (xn * yn);
        int tv   = targets[b * (T + 1) + t];
        bool msk = (t == 0) || (tv > 0);
        g_w[b * T + t] = msk ? w : -1.0f;
    }
}

// ---------------------------------------------------------------------------
// Kernel 2: per-batch top-k (k=51), descending, stable by index (jax top_k).
// Bitonic sort of 512 packed keys in smem; also counts seq_len -> m.
// ---------------------------------------------------------------------------
__global__ __launch_bounds__(512) void k_topk(const int* __restrict__ targets)
{
    __shared__ unsigned long long keys[T];
    __shared__ int cnt;
    const int b   = blockIdx.x;
    const int tid = threadIdx.x;

    if (tid == 0) cnt = 0;
    __syncthreads();

    float w = g_w[b * T + tid];
    unsigned uf = __float_as_uint(w);
    uf = (uf & 0x80000000u) ? ~uf : (uf | 0x80000000u);   // monotone-increasing map
    keys[tid] = ((unsigned long long)uf << 32) | (unsigned)(T - 1 - tid);

    int tv = targets[b * (T + 1) + tid];
    if ((tid == 0) || (tv > 0)) atomicAdd(&cnt, 1);
    __syncthreads();

    // Bitonic sort, overall descending
    for (int size = 2; size <= T; size <<= 1) {
        for (int stride = size >> 1; stride > 0; stride >>= 1) {
            __syncthreads();
            int ixj = tid ^ stride;
            if (ixj > tid) {
                bool desc = ((tid & size) == 0);
                unsigned long long a = keys[tid], bk = keys[ixj];
                bool sw = desc ? (a < bk) : (a > bk);
                if (sw) { keys[tid] = bk; keys[ixj] = a; }
            }
        }
    }
    __syncthreads();

    if (tid < K_TOP) {
        unsigned long long kk = keys[tid];
        unsigned hu = (unsigned)(kk >> 32);
        unsigned orig = (hu & 0x80000000u) ? (hu ^ 0x80000000u) : ~hu;
        g_selw[b * K_TOP + tid]   = __uint_as_float(orig);
        g_selidx[b * K_TOP + tid] = (T - 1) - (int)(kk & 0xffffffffull);
    }
    if (tid == 0) {
        int sl = cnt;
        int m = (int)ceilf((float)sl * 0.1f);
        g_m[b] = m < K_TOP ? m : K_TOP;
    }
}

// ---------------------------------------------------------------------------
// Kernel 3: gather top-m rows of layer-2 attention, mean over H, relu(w*.),
// sum / m, then per-batch min/max normalize. One block per b, thread per s.
// j unrolled x4, h x8 -> 32 concurrent loads to hide DRAM latency.
// ---------------------------------------------------------------------------
__global__ __launch_bounds__(256) void k_gather(
    const float* __restrict__ attns,   // (L, B, H, T, S)
    float* __restrict__ out)           // (B, S)
{
    __shared__ float smw[K_TOP];
    __shared__ int   smi[K_TOP];
    __shared__ int   sm_m;
    __shared__ float rmin[256], rmax[256];
    __shared__ float s_mn, s_mx;

    const int b   = blockIdx.x;
    const int tid = threadIdx.x;

    if (tid < K_TOP) { smw[tid] = g_selw[b * K_TOP + tid]; smi[tid] = g_selidx[b * K_TOP + tid]; }
    if (tid == 0) sm_m = g_m[b];
    __syncthreads();

    const int m = sm_m;
    const float* base = attns + (((size_t)LAYER_ID * B + b) * H) * (size_t)(T * S);

    float acc = 0.f;
    const bool active = (tid < S);
    if (active) {
        for (int j0 = 0; j0 < 52; j0 += 4) {
            float wj[4]; int tj[4];
#pragma unroll
            for (int jj = 0; jj < 4; jj++) {
                int j = j0 + jj;
                wj[jj] = (j < m) ? smw[j] : 0.0f;
                tj[jj] = (j < K_TOP) ? smi[j] : 0;
            }
            float v[4][8];
#pragma unroll
            for (int jj = 0; jj < 4; jj++) {
                const float* p = base + (size_t)tj[jj] * S + tid;
#pragma unroll
                for (int h = 0; h < H; h++)
                    v[jj][h] = __ldg(p + (size_t)h * T * S);
            }
#pragma unroll
            for (int jj = 0; jj < 4; jj++) {
                float hs = 0.f;
#pragma unroll
                for (int h = 0; h < H; h++) hs += v[jj][h];
                acc += fmaxf(wj[jj] * (hs * 0.125f), 0.0f);
            }
        }
        acc /= (float)m;
    }

    rmin[tid] = active ? acc :  CUDART_INF_F;
    rmax[tid] = active ? acc : -CUDART_INF_F;
    __syncthreads();
    for (int o = 128; o > 0; o >>= 1) {
        if (tid < o) {
            rmin[tid] = fminf(rmin[tid], rmin[tid + o]);
            rmax[tid] = fmaxf(rmax[tid], rmax[tid + o]);
        }
        __syncthreads();
    }
    if (tid == 0) { s_mn = rmin[0]; s_mx = rmax[0]; }
    __syncthreads();

    if (active) {
        float mn = s_mn, mx = s_mx;
        out[b * S + tid] = (acc - mn) / fmaxf(mx - mn, 1e-12f);
    }
}

// ---------------------------------------------------------------------------
extern "C" void kernel_launch(void* const* d_in, const int* in_sizes, int n_in,
                              void* d_out, int out_size)
{
    const float* fore    = (const float*)d_in[0];  // (B, D)
    const float* embed   = (const float*)d_in[1];  // (B, T, D)
    const float* attns   = (const float*)d_in[2];  // (L, B, H, T, S)
    const int*   targets = (const int*)  d_in[3];  // (B, T+1) int32
    float* out = (float*)d_out;

    dim3 g1(T / 8, B);
    k_weights<<<g1, 256>>>(fore, embed, targets);
    k_topk<<<B, 512>>>(targets);
    k_gather<<<B, 256>>>(attns, out);
}

// round 2
// speedup vs baseline: 1.5023x; 1.5023x over previous
#include <cuda_runtime.h>
#include <math_constants.h>

// Shapes (fixed by problem)
#define B 32
#define T 512
#define D 512
#define H 8
#define S 196
#define LAYER_ID 2
#define K_TOP 51   // int(0.1 * 512)
#define NJC 4      // j-chunks in gather

// Scratch (allocation-free rule: __device__ globals)
__device__ float g_w[B * T];
__device__ int   g_selidx[B * K_TOP];
__device__ float g_selw[B * K_TOP];
__device__ int   g_m[B];
__device__ float g_part[B][NJC][S];

// ---------------------------------------------------------------------------
// Kernel 1: cosine weights. One warp handles TWO t-rows (12 LDG.128/thread),
// no smem, no syncthreads. grid (T/16, B), 256 threads.
// ---------------------------------------------------------------------------
__global__ __launch_bounds__(256) void k_weights(
    const float* __restrict__ fore,     // (B, D)
    const float* __restrict__ embed,    // (B, T, D)
    const int*   __restrict__ targets)  // (B, T+1) int32
{
    const int b    = blockIdx.y;
    const int lane = threadIdx.x & 31;
    const int warp = threadIdx.x >> 5;
    const int t0   = (blockIdx.x * 8 + warp) * 2;

    const float4* yrow = reinterpret_cast<const float4*>(fore + (size_t)b * D);
    const float4* x0   = reinterpret_cast<const float4*>(embed + ((size_t)b * T + t0) * D);
    const float4* x1   = x0 + D / 4;

    float4 yv[4], xa[4], xb[4];
#pragma unroll
    for (int i = 0; i < 4; i++) {
        yv[i] = __ldg(&yrow[lane + i * 32]);
        xa[i] = __ldg(&x0[lane + i * 32]);
        xb[i] = __ldg(&x1[lane + i * 32]);
    }

    float n0 = 0.f, n1 = 0.f, xs0 = 0.f, xs1 = 0.f, ys = 0.f;
#pragma unroll
    for (int i = 0; i < 4; i++) {
        float4 y = yv[i], a = xa[i], c = xb[i];
        ys  += y.x * y.x + y.y * y.y + y.z * y.z + y.w * y.w;
        n0  += a.x * y.x + a.y * y.y + a.z * y.z + a.w * y.w;
        xs0 += a.x * a.x + a.y * a.y + a.z * a.z + a.w * a.w;
        n1  += c.x * y.x + c.y * y.y + c.z * y.z + c.w * y.w;
        xs1 += c.x * c.x + c.y * c.y + c.z * c.z + c.w * c.w;
    }
#pragma unroll
    for (int o = 16; o; o >>= 1) {
        n0  += __shfl_xor_sync(0xffffffffu, n0,  o);
        n1  += __shfl_xor_sync(0xffffffffu, n1,  o);
        xs0 += __shfl_xor_sync(0xffffffffu, xs0, o);
        xs1 += __shfl_xor_sync(0xffffffffu, xs1, o);
        ys  += __shfl_xor_sync(0xffffffffu, ys,  o);
    }
    if (lane < 2) {
        const int t = t0 + lane;
        float num = lane ? n1 : n0;
        float xn2 = lane ? xs1 : xs0;
        float xn  = fmaxf(sqrtf(xn2), 1e-8f);
        float yn  = fmaxf(sqrtf(ys),  1e-8f);
        float w   = num / (xn * yn);
        int tv    = targets[b * (T + 1) + t];
        bool msk  = (t == 0) || (tv > 0);
        g_w[b * T + t] = msk ? w : -1.0f;
    }
}

// ---------------------------------------------------------------------------
// Kernel 2: per-batch top-k (k=51), descending, stable by index (jax top_k).
// Bitonic sort of 512 packed keys in smem; also counts seq_len -> m.
// ---------------------------------------------------------------------------
__global__ __launch_bounds__(512) void k_topk(const int* __restrict__ targets)
{
    __shared__ unsigned long long keys[T];
    __shared__ int cnt;
    const int b   = blockIdx.x;
    const int tid = threadIdx.x;

    if (tid == 0) cnt = 0;
    __syncthreads();

    float w = g_w[b * T + tid];
    unsigned uf = __float_as_uint(w);
    uf = (uf & 0x80000000u) ? ~uf : (uf | 0x80000000u);   // monotone-increasing map
    keys[tid] = ((unsigned long long)uf << 32) | (unsigned)(T - 1 - tid);

    int tv = targets[b * (T + 1) + tid];
    if ((tid == 0) || (tv > 0)) atomicAdd(&cnt, 1);
    __syncthreads();

    for (int size = 2; size <= T; size <<= 1) {
        for (int stride = size >> 1; stride > 0; stride >>= 1) {
            __syncthreads();
            int ixj = tid ^ stride;
            if (ixj > tid) {
                bool desc = ((tid & size) == 0);
                unsigned long long a = keys[tid], bk = keys[ixj];
                bool sw = desc ? (a < bk) : (a > bk);
                if (sw) { keys[tid] = bk; keys[ixj] = a; }
            }
        }
    }
    __syncthreads();

    if (tid < K_TOP) {
        unsigned long long kk = keys[tid];
        unsigned hu = (unsigned)(kk >> 32);
        unsigned orig = (hu & 0x80000000u) ? (hu ^ 0x80000000u) : ~hu;
        g_selw[b * K_TOP + tid]   = __uint_as_float(orig);
        g_selidx[b * K_TOP + tid] = (T - 1) - (int)(kk & 0xffffffffull);
    }
    if (tid == 0) {
        int sl = cnt;
        int m = (int)ceilf((float)sl * 0.1f);
        g_m[b] = m < K_TOP ? m : K_TOP;
    }
}

// ---------------------------------------------------------------------------
// Kernel 3: gather. grid (NJC, B). Chunk c handles j = c, c+4, ... (13 j's),
// writes partial sum to g_part[b][c][s]. j unrolled x2, h x8 -> 16 MLP.
// ---------------------------------------------------------------------------
__global__ __launch_bounds__(256) void k_gather(const float* __restrict__ attns)
{
    __shared__ float smw[14];
    __shared__ int   smi[14];
    __shared__ int   sm_m;

    const int c   = blockIdx.x;
    const int b   = blockIdx.y;
    const int tid = threadIdx.x;

    if (tid == 0) sm_m = g_m[b];
    if (tid < 14) {
        int j = c + NJC * tid;
        smw[tid] = (j < K_TOP) ? g_selw[b * K_TOP + j] : 0.f;
        smi[tid] = (j < K_TOP) ? g_selidx[b * K_TOP + j] : 0;
    }
    __syncthreads();

    if (tid >= S) return;
    const int m = sm_m;
    const float* base = attns + ((size_t)(LAYER_ID * B + b)) * H * T * S;

    float acc = 0.f;
#pragma unroll
    for (int i = 0; i < 14; i += 2) {
        int j0 = c + NJC * i;
        int j1 = j0 + NJC;
        float w0 = (j0 < m) ? smw[i]     : 0.f;
        float w1 = (j1 < m) ? smw[i + 1] : 0.f;
        int   r0 = smi[i], r1 = smi[i + 1];

        float v0[8], v1[8];
        const float* p0 = base + (size_t)r0 * S + tid;
        const float* p1 = base + (size_t)r1 * S + tid;
#pragma unroll
        for (int h = 0; h < H; h++) {
            v0[h] = __ldg(p0 + (size_t)h * T * S);
            v1[h] = __ldg(p1 + (size_t)h * T * S);
        }
        float h0 = 0.f, h1 = 0.f;
#pragma unroll
        for (int h = 0; h < H; h++) { h0 += v0[h]; h1 += v1[h]; }
        acc += fmaxf(w0 * (h0 * 0.125f), 0.f) + fmaxf(w1 * (h1 * 0.125f), 0.f);
    }
    g_part[b][c][tid] = acc;
}

// ---------------------------------------------------------------------------
// Kernel 4: merge partials, /m, per-batch min-max normalize. grid B.
// ---------------------------------------------------------------------------
__global__ __launch_bounds__(256) void k_norm(float* __restrict__ out)
{
    __shared__ float rmin[256], rmax[256];
    __shared__ float s_mn, s_mx;

    const int b   = blockIdx.x;
    const int tid = threadIdx.x;
    const bool active = (tid < S);

    float acc = 0.f;
    if (active) {
#pragma unroll
        for (int c = 0; c < NJC; c++) acc += g_part[b][c][tid];
        acc /= (float)g_m[b];
    }

    rmin[tid] = active ? acc :  CUDART_INF_F;
    rmax[tid] = active ? acc : -CUDART_INF_F;
    __syncthreads();
    for (int o = 128; o > 0; o >>= 1) {
        if (tid < o) {
            rmin[tid] = fminf(rmin[tid], rmin[tid + o]);
            rmax[tid] = fmaxf(rmax[tid], rmax[tid + o]);
        }
        __syncthreads();
    }
    if (tid == 0) { s_mn = rmin[0]; s_mx = rmax[0]; }
    __syncthreads();

    if (active)
        out[b * S + tid] = (acc - s_mn) / fmaxf(s_mx - s_mn, 1e-12f);
}

// ---------------------------------------------------------------------------
extern "C" void kernel_launch(void* const* d_in, const int* in_sizes, int n_in,
                              void* d_out, int out_size)
{
    const float* fore    = (const float*)d_in[0];  // (B, D)
    const float* embed   = (const float*)d_in[1];  // (B, T, D)
    const float* attns   = (const float*)d_in[2];  // (L, B, H, T, S)
    const int*   targets = (const int*)  d_in[3];  // (B, T+1) int32
    float* out = (float*)d_out;

    k_weights<<<dim3(T / 16, B), 256>>>(fore, embed, targets);
    k_topk<<<B, 512>>>(targets);
    k_gather<<<dim3(NJC, B), 256>>>(attns);
    k_norm<<<B, 256>>>(out);
}

// round 3
// speedup vs baseline: 1.6538x; 1.1008x over previous
#include <cuda_runtime.h>
#include <math_constants.h>

// Shapes (fixed by problem)
#define B 32
#define T 512
#define D 512
#define H 8
#define S 196
#define LAYER_ID 2
#define K_TOP 51   // int(0.1 * 512)
#define NJC 5      // j-groups inside fused kernel (5*196 = 980 <= 1024 threads)

// Scratch (allocation-free rule: __device__ globals)
__device__ float g_w[B * T];

// ---------------------------------------------------------------------------
// Kernel 1: cosine weights. One warp handles TWO t-rows (12 LDG.128/thread),
// no smem, no syncthreads. grid (T/16, B), 256 threads.
// ---------------------------------------------------------------------------
__global__ __launch_bounds__(256) void k_weights(
    const float* __restrict__ fore,     // (B, D)
    const float* __restrict__ embed,    // (B, T, D)
    const int*   __restrict__ targets)  // (B, T+1) int32
{
    const int b    = blockIdx.y;
    const int lane = threadIdx.x & 31;
    const int warp = threadIdx.x >> 5;
    const int t0   = (blockIdx.x * 8 + warp) * 2;

    const float4* yrow = reinterpret_cast<const float4*>(fore + (size_t)b * D);
    const float4* x0   = reinterpret_cast<const float4*>(embed + ((size_t)b * T + t0) * D);
    const float4* x1   = x0 + D / 4;

    float4 yv[4], xa[4], xb[4];
#pragma unroll
    for (int i = 0; i < 4; i++) {
        yv[i] = __ldg(&yrow[lane + i * 32]);
        xa[i] = __ldg(&x0[lane + i * 32]);
        xb[i] = __ldg(&x1[lane + i * 32]);
    }

    float n0 = 0.f, n1 = 0.f, xs0 = 0.f, xs1 = 0.f, ys = 0.f;
#pragma unroll
    for (int i = 0; i < 4; i++) {
        float4 y = yv[i], a = xa[i], c = xb[i];
        ys  += y.x * y.x + y.y * y.y + y.z * y.z + y.w * y.w;
        n0  += a.x * y.x + a.y * y.y + a.z * y.z + a.w * y.w;
        xs0 += a.x * a.x + a.y * a.y + a.z * a.z + a.w * a.w;
        n1  += c.x * y.x + c.y * y.y + c.z * y.z + c.w * y.w;
        xs1 += c.x * c.x + c.y * c.y + c.z * c.z + c.w * c.w;
    }
#pragma unroll
    for (int o = 16; o; o >>= 1) {
        n0  += __shfl_xor_sync(0xffffffffu, n0,  o);
        n1  += __shfl_xor_sync(0xffffffffu, n1,  o);
        xs0 += __shfl_xor_sync(0xffffffffu, xs0, o);
        xs1 += __shfl_xor_sync(0xffffffffu, xs1, o);
        ys  += __shfl_xor_sync(0xffffffffu, ys,  o);
    }
    if (lane < 2) {
        const int t = t0 + lane;
        float num = lane ? n1 : n0;
        float xn2 = lane ? xs1 : xs0;
        float xn  = fmaxf(sqrtf(xn2), 1e-8f);
        float yn  = fmaxf(sqrtf(ys),  1e-8f);
        float w   = num / (xn * yn);
        int tv    = targets[b * (T + 1) + t];
        bool msk  = (t == 0) || (tv > 0);
        g_w[b * T + t] = msk ? w : -1.0f;
    }
}

// ---------------------------------------------------------------------------
// Kernel 2 (fused): per-batch top-k (bitonic, stable like jax top_k) +
// gather top-m attention rows + mean over H + relu(w*.) + sum/m + min-max
// normalize. One block of 1024 threads per batch b.
// ---------------------------------------------------------------------------
__global__ __launch_bounds__(1024) void k_fused(
    const int*   __restrict__ targets,  // (B, T+1) int32
    const float* __restrict__ attns,    // (L, B, H, T, S)
    float*       __restrict__ out)      // (B, S)
{
    __shared__ unsigned long long keys[T];
    __shared__ float smw[K_TOP + NJC];
    __shared__ int   smi[K_TOP + NJC];
    __shared__ int   cnt;
    __shared__ int   sm_m;
    __shared__ float part[NJC][S];
    __shared__ float rmin[256], rmax[256];
    __shared__ float s_mn, s_mx;

    const int b   = blockIdx.x;
    const int tid = threadIdx.x;

    // ---- Phase 1: build sort keys + count seq_len
    if (tid == 0) cnt = 0;
    __syncthreads();

    if (tid < T) {
        float w = g_w[b * T + tid];
        unsigned uf = __float_as_uint(w);
        uf = (uf & 0x80000000u) ? ~uf : (uf | 0x80000000u);   // order-preserving map
        keys[tid] = ((unsigned long long)uf << 32) | (unsigned)(T - 1 - tid);
        int tv = targets[b * (T + 1) + tid];
        if ((tid == 0) || (tv > 0)) atomicAdd(&cnt, 1);
    }
    __syncthreads();

    // ---- Phase 2: bitonic sort (descending), 512 workers, all sync
    for (int size = 2; size <= T; size <<= 1) {
        for (int stride = size >> 1; stride > 0; stride >>= 1) {
            if (tid < T) {
                int ixj = tid ^ stride;
                if (ixj > tid) {
                    bool desc = ((tid & size) == 0);
                    unsigned long long a = keys[tid], bk = keys[ixj];
                    bool sw = desc ? (a < bk) : (a > bk);
                    if (sw) { keys[tid] = bk; keys[ixj] = a; }
                }
            }
            __syncthreads();
        }
    }

    // ---- Phase 3: unpack top-k, compute m
    if (tid < K_TOP) {
        unsigned long long kk = keys[tid];
        unsigned hu = (unsigned)(kk >> 32);
        unsigned orig = (hu & 0x80000000u) ? (hu ^ 0x80000000u) : ~hu;
        smw[tid] = __uint_as_float(orig);
        smi[tid] = (T - 1) - (int)(kk & 0xffffffffull);
    }
    if (tid >= K_TOP && tid < K_TOP + NJC) { smw[tid] = 0.f; smi[tid] = 0; }
    if (tid == 0) {
        int m = (int)ceilf((float)cnt * 0.1f);
        sm_m = m < K_TOP ? m : K_TOP;
    }
    __syncthreads();

    // ---- Phase 4: gather. 980 active threads: c = tid/S in [0,5), s = tid%S.
    const int m = sm_m;
    const int c = tid / S;
    const int s = tid - c * S;
    if (c < NJC) {
        const float* base = attns + ((size_t)(LAYER_ID * B + b)) * H * T * S + s;
        float acc = 0.f;
        // j = c, c+5, ..., up to < m (<= 11 iterations); unroll x2 for MLP
#pragma unroll
        for (int i = 0; i < 12; i += 2) {
            int j0 = c + NJC * i;
            int j1 = j0 + NJC;
            bool a0 = (j0 < m), a1 = (j1 < m);
            if (!a0) break;
            float w0 = smw[j0];
            float w1 = a1 ? smw[j1] : 0.f;
            int   r0 = smi[j0];
            int   r1 = a1 ? smi[j1] : r0;
            const float* p0 = base + (size_t)r0 * S;
            const float* p1 = base + (size_t)r1 * S;
            float v0[8], v1[8];
#pragma unroll
            for (int h = 0; h < H; h++) {
                v0[h] = __ldg(p0 + (size_t)h * T * S);
                v1[h] = __ldg(p1 + (size_t)h * T * S);
            }
            float h0 = 0.f, h1 = 0.f;
#pragma unroll
            for (int h = 0; h < H; h++) { h0 += v0[h]; h1 += v1[h]; }
            acc += fmaxf(w0 * (h0 * 0.125f), 0.f);
            if (a1) acc += fmaxf(w1 * (h1 * 0.125f), 0.f);
        }
        part[c][s] = acc;
    }
    __syncthreads();

    // ---- Phase 5: merge j-groups, /m, min-max normalize over s
    float acc = 0.f;
    const bool active = (tid < S);
    if (active) {
#pragma unroll
        for (int cc = 0; cc < NJC; cc++) acc += part[cc][tid];
        acc /= (float)m;
    }
    if (tid < 256) {
        rmin[tid] = active ? acc :  CUDART_INF_F;
        rmax[tid] = active ? acc : -CUDART_INF_F;
    }
    __syncthreads();
    for (int o = 128; o > 0; o >>= 1) {
        if (tid < o) {
            rmin[tid] = fminf(rmin[tid], rmin[tid + o]);
            rmax[tid] = fmaxf(rmax[tid], rmax[tid + o]);
        }
        __syncthreads();
    }
    if (tid == 0) { s_mn = rmin[0]; s_mx = rmax[0]; }
    __syncthreads();

    if (active)
        out[b * S + tid] = (acc - s_mn) / fmaxf(s_mx - s_mn, 1e-12f);
}

// ---------------------------------------------------------------------------
extern "C" void kernel_launch(void* const* d_in, const int* in_sizes, int n_in,
                              void* d_out, int out_size)
{
    const float* fore    = (const float*)d_in[0];  // (B, D)
    const float* embed   = (const float*)d_in[1];  // (B, T, D)
    const float* attns   = (const float*)d_in[2];  // (L, B, H, T, S)
    const int*   targets = (const int*)  d_in[3];  // (B, T+1) int32
    float* out = (float*)d_out;

    k_weights<<<dim3(T / 16, B), 256>>>(fore, embed, targets);
    k_fused<<<B, 1024>>>(targets, attns, out);
}